// round 1
// baseline (speedup 1.0000x reference)
#include <cuda_runtime.h>
#include <cuda_bf16.h>
#include <math.h>

// Problem constants
#define BATCH 64
#define TT    1024
#define DIN   64
#define HID   128
#define G3    384   // 3*HID
#define D2    256   // 2*HID
#define MROWS (BATCH*TT)   // 65536

// ---------------- scratch (device globals; no allocation allowed) ----------
__device__ float g_xW[2][MROWS][G3];   // per-dir input projections (reused L0/L1)
__device__ float g_z0[MROWS][D2];      // layer-0 output [b*T+t][256]
__device__ float g_z1[MROWS][D2];      // layer-1 output

// ---------------- input projection GEMM: C = A @ W^T + bias ----------------
// A: [MROWS, K] row-major (K = 64 for layer0 [x], 256 for layer1 [g_z0])
// W: [384, K] row-major, bias: [384]
// writes g_xW[dir][m][n];  grid.z = dir
__global__ __launch_bounds__(256)
void proj_gemm_kernel(const float* __restrict__ A0,
                      const float* __restrict__ Wf, const float* __restrict__ Wb,
                      const float* __restrict__ bf, const float* __restrict__ bb,
                      int K, int layer)
{
    constexpr int BM = 128, BN = 64, BK = 16;
    __shared__ float As[BK][BM + 4];
    __shared__ float Ws[BK][BN + 4];

    const int dir = blockIdx.z;
    const float* __restrict__ A    = layer ? (const float*)g_z0 : A0;
    const float* __restrict__ Wp   = dir ? Wb : Wf;
    const float* __restrict__ bias = dir ? bb : bf;

    const int m0 = blockIdx.x * BM;
    const int n0 = blockIdx.y * BN;

    const int tid  = threadIdx.x;
    const int arow = tid >> 2;           // 0..63
    const int kq   = (tid & 3) * 4;      // 0,4,8,12
    const int tx   = tid & 15;           // N micro (4)
    const int ty   = tid >> 4;           // M micro (8)

    float acc[8][4];
    #pragma unroll
    for (int i = 0; i < 8; ++i)
        #pragma unroll
        for (int j = 0; j < 4; ++j) acc[i][j] = 0.f;

    for (int k0 = 0; k0 < K; k0 += BK) {
        // load A tile (128 x 16) transposed into As
        {
            const float* p = A + (size_t)(m0 + arow) * K + k0 + kq;
            float4 v0 = *(const float4*)p;
            float4 v1 = *(const float4*)(p + (size_t)64 * K);
            As[kq + 0][arow] = v0.x; As[kq + 1][arow] = v0.y;
            As[kq + 2][arow] = v0.z; As[kq + 3][arow] = v0.w;
            As[kq + 0][arow + 64] = v1.x; As[kq + 1][arow + 64] = v1.y;
            As[kq + 2][arow + 64] = v1.z; As[kq + 3][arow + 64] = v1.w;
        }
        // load W tile (64 x 16) transposed into Ws
        {
            const float* p = Wp + (size_t)(n0 + arow) * K + k0 + kq;
            float4 v = *(const float4*)p;
            Ws[kq + 0][arow] = v.x; Ws[kq + 1][arow] = v.y;
            Ws[kq + 2][arow] = v.z; Ws[kq + 3][arow] = v.w;
        }
        __syncthreads();

        #pragma unroll
        for (int kk = 0; kk < BK; ++kk) {
            float4 a0 = *(const float4*)&As[kk][ty * 8];
            float4 a1 = *(const float4*)&As[kk][ty * 8 + 4];
            float4 w4 = *(const float4*)&Ws[kk][tx * 4];
            float av[8] = {a0.x, a0.y, a0.z, a0.w, a1.x, a1.y, a1.z, a1.w};
            float wv[4] = {w4.x, w4.y, w4.z, w4.w};
            #pragma unroll
            for (int i = 0; i < 8; ++i)
                #pragma unroll
                for (int j = 0; j < 4; ++j)
                    acc[i][j] += av[i] * wv[j];
        }
        __syncthreads();
    }

    float* Cout = &g_xW[dir][0][0];
    float4 b4 = *(const float4*)(bias + n0 + tx * 4);
    float* Crow = Cout + (size_t)(m0 + ty * 8) * G3 + n0 + tx * 4;
    #pragma unroll
    for (int i = 0; i < 8; ++i) {
        float4 o;
        o.x = acc[i][0] + b4.x; o.y = acc[i][1] + b4.y;
        o.z = acc[i][2] + b4.z; o.w = acc[i][3] + b4.w;
        *(float4*)(Crow + (size_t)i * G3) = o;
    }
}

// ---------------- GRU recurrence -------------------------------------------
// one block per (batch, dir); 384 threads, Whh row-per-thread in registers
__global__ __launch_bounds__(384, 1)
void gru_scan_kernel(const float* __restrict__ whh_f, const float* __restrict__ whh_b,
                     const float* __restrict__ bhh_f, const float* __restrict__ bhh_b,
                     int layer)
{
    const int b   = blockIdx.x >> 1;
    const int dir = blockIdx.x & 1;
    const int j   = threadIdx.x;                 // 0..383

    const float* __restrict__ whh = dir ? whh_b : whh_f;
    const float* __restrict__ bhh = dir ? bhh_b : bhh_f;

    __shared__ __align__(16) float h_s[HID];
    __shared__ float gh_s[G3];
    __shared__ float gi_s[G3];

    // load Whh row j into registers (128 floats)
    float w[HID];
    #pragma unroll
    for (int k = 0; k < HID; k += 4) {
        float4 v = *(const float4*)(whh + (size_t)j * HID + k);
        w[k] = v.x; w[k + 1] = v.y; w[k + 2] = v.z; w[k + 3] = v.w;
    }
    const float bj = bhh[j];
    if (j < HID) h_s[j] = 0.f;

    const float* __restrict__ gi = &g_xW[dir][(size_t)b * TT][0];
    float* __restrict__ zout = (layer ? &g_z1[(size_t)b * TT][0]
                                      : &g_z0[(size_t)b * TT][0]);
    __syncthreads();

    for (int t = 0; t < TT; ++t) {
        const int tt = dir ? (TT - 1 - t) : t;
        float g = __ldg(gi + (size_t)tt * G3 + j);   // hidden under dot phase

        float a0 = bj, a1 = 0.f, a2 = 0.f, a3 = 0.f;
        #pragma unroll
        for (int k = 0; k < HID; k += 4) {
            float4 hv = *(const float4*)(h_s + k);   // broadcast LDS
            a0 += w[k]     * hv.x;
            a1 += w[k + 1] * hv.y;
            a2 += w[k + 2] * hv.z;
            a3 += w[k + 3] * hv.w;
        }
        gh_s[j] = (a0 + a1) + (a2 + a3);
        gi_s[j] = g;
        __syncthreads();

        if (j < HID) {
            float r  = 1.f / (1.f + __expf(-(gi_s[j]         + gh_s[j])));
            float zg = 1.f / (1.f + __expf(-(gi_s[HID + j]   + gh_s[HID + j])));
            float n  = tanhf(gi_s[2 * HID + j] + r * gh_s[2 * HID + j]);
            float hn = (1.f - zg) * n + zg * h_s[j];
            h_s[j] = hn;
            zout[(size_t)tt * D2 + dir * HID + j] = hn;
        }
        __syncthreads();
    }
}

// ---------------- attention pooling + heads --------------------------------
__global__ __launch_bounds__(256)
void attn_head_kernel(const float* __restrict__ attn_w, const float* __restrict__ attn_b,
                      const float* __restrict__ motor_w, const float* __restrict__ motor_b,
                      const float* __restrict__ state_w, const float* __restrict__ state_b,
                      const int* __restrict__ motor_k, float* __restrict__ out)
{
    const int b = blockIdx.x;
    const int tid = threadIdx.x;       // 256 threads
    const int warp = tid >> 5, lane = tid & 31;

    __shared__ float sw[D2];
    __shared__ float sc[TT];
    __shared__ float red[256];
    __shared__ float pooled[D2];

    sw[tid] = attn_w[tid];
    __syncthreads();

    const float* __restrict__ zb = &g_z1[(size_t)b * TT][0];
    const float ab = attn_b[0];

    // scores[t] = z[b,t,:] . attn_w + attn_b
    for (int t = warp; t < TT; t += 8) {
        const float* zt = zb + (size_t)t * D2;
        float s = 0.f;
        #pragma unroll
        for (int d = lane; d < D2; d += 32) s += zt[d] * sw[d];
        #pragma unroll
        for (int o = 16; o; o >>= 1) s += __shfl_xor_sync(0xffffffffu, s, o);
        if (lane == 0) sc[t] = s + ab;
    }
    __syncthreads();

    // softmax over T
    float m = -INFINITY;
    for (int t = tid; t < TT; t += 256) m = fmaxf(m, sc[t]);
    red[tid] = m; __syncthreads();
    for (int s = 128; s; s >>= 1) {
        if (tid < s) red[tid] = fmaxf(red[tid], red[tid + s]);
        __syncthreads();
    }
    m = red[0]; __syncthreads();

    float sum = 0.f;
    for (int t = tid; t < TT; t += 256) {
        float e = __expf(sc[t] - m);
        sc[t] = e;
        sum += e;
    }
    red[tid] = sum; __syncthreads();
    for (int s = 128; s; s >>= 1) {
        if (tid < s) red[tid] += red[tid + s];
        __syncthreads();
    }
    const float inv = 1.f / red[0];
    __syncthreads();

    // pooled[d] = sum_t a[t] * z[b,t,d]
    float acc = 0.f;
    #pragma unroll 8
    for (int t = 0; t < TT; ++t) acc += sc[t] * zb[(size_t)t * D2 + tid];
    pooled[tid] = acc * inv;
    __syncthreads();

    // heads: 5 motor logits + 2 state logits, one warp each
    if (warp < 7) {
        const float* wv;
        float bv;
        int mk = motor_k[b];
        if (warp < 5) { wv = motor_w + warp * D2;              bv = motor_b[warp]; }
        else          { int c = warp - 5;
                        wv = state_w + (size_t)(mk * 2 + c) * D2;
                        bv = state_b[mk * 2 + c]; }
        float s = 0.f;
        #pragma unroll
        for (int d = lane; d < D2; d += 32) s += pooled[d] * wv[d];
        #pragma unroll
        for (int o = 16; o; o >>= 1) s += __shfl_xor_sync(0xffffffffu, s, o);
        if (lane == 0) {
            if (warp < 5) out[b * 5 + warp] = s + bv;
            else          out[BATCH * 5 + b * 2 + (warp - 5)] = s + bv;
        }
    }
}

// ---------------- launch ----------------------------------------------------
extern "C" void kernel_launch(void* const* d_in, const int* in_sizes, int n_in,
                              void* d_out, int out_size)
{
    const float* x        = (const float*)d_in[0];
    const int*   motor_k  = (const int*)  d_in[1];
    const float* wih_l0f  = (const float*)d_in[2];
    const float* whh_l0f  = (const float*)d_in[3];
    const float* bih_l0f  = (const float*)d_in[4];
    const float* bhh_l0f  = (const float*)d_in[5];
    const float* wih_l0b  = (const float*)d_in[6];
    const float* whh_l0b  = (const float*)d_in[7];
    const float* bih_l0b  = (const float*)d_in[8];
    const float* bhh_l0b  = (const float*)d_in[9];
    const float* wih_l1f  = (const float*)d_in[10];
    const float* whh_l1f  = (const float*)d_in[11];
    const float* bih_l1f  = (const float*)d_in[12];
    const float* bhh_l1f  = (const float*)d_in[13];
    const float* wih_l1b  = (const float*)d_in[14];
    const float* whh_l1b  = (const float*)d_in[15];
    const float* bih_l1b  = (const float*)d_in[16];
    const float* bhh_l1b  = (const float*)d_in[17];
    const float* attn_w   = (const float*)d_in[18];
    const float* attn_b   = (const float*)d_in[19];
    const float* motor_w  = (const float*)d_in[20];
    const float* motor_b  = (const float*)d_in[21];
    const float* state_w  = (const float*)d_in[22];
    const float* state_b  = (const float*)d_in[23];
    float* out = (float*)d_out;

    dim3 gproj(MROWS / 128, G3 / 64, 2);

    // layer 0
    proj_gemm_kernel<<<gproj, 256>>>(x, wih_l0f, wih_l0b, bih_l0f, bih_l0b, DIN, 0);
    gru_scan_kernel<<<BATCH * 2, 384>>>(whh_l0f, whh_l0b, bhh_l0f, bhh_l0b, 0);
    // layer 1
    proj_gemm_kernel<<<gproj, 256>>>(nullptr, wih_l1f, wih_l1b, bih_l1f, bih_l1b, D2, 1);
    gru_scan_kernel<<<BATCH * 2, 384>>>(whh_l1f, whh_l1b, bhh_l1f, bhh_l1b, 1);
    // pooling + heads
    attn_head_kernel<<<BATCH, 256>>>(attn_w, attn_b, motor_w, motor_b,
                                     state_w, state_b, motor_k, out);
}

// round 2
// speedup vs baseline: 1.0810x; 1.0810x over previous
#include <cuda_runtime.h>
#include <cuda_bf16.h>
#include <math.h>

// Problem constants
#define BATCH 64
#define TT    1024
#define DIN   64
#define HID   128
#define G3    384   // 3*HID
#define D2    256   // 2*HID
#define MROWS (BATCH*TT)   // 65536

typedef unsigned long long ull;

// ---------------- f32x2 packed helpers (sm_103a FFMA2) ----------------------
__device__ __forceinline__ ull fma2(ull a, ull b, ull c) {
    ull d;
    asm("fma.rn.f32x2 %0, %1, %2, %3;" : "=l"(d) : "l"(a), "l"(b), "l"(c));
    return d;
}
__device__ __forceinline__ ull pack2(float lo, float hi) {
    ull d;
    asm("mov.b64 %0, {%1, %2};" : "=l"(d) : "f"(lo), "f"(hi));
    return d;
}
__device__ __forceinline__ float2 unpack2(ull v) {
    float2 r;
    asm("mov.b64 {%0, %1}, %2;" : "=f"(r.x), "=f"(r.y) : "l"(v));
    return r;
}
__device__ __forceinline__ float sigm(float x) {
    return 1.f / (1.f + __expf(-x));
}
__device__ __forceinline__ float ftanh(float x) {
    // tanh(x) = 2/(1+e^{-2x}) - 1 ; exact enough (~1e-7) via MUFU EX2 path
    return __fmaf_rn(2.f, 1.f / (1.f + __expf(-2.f * x)), -1.f);
}

// ---------------- scratch (device globals; no allocation allowed) ----------
__device__ float g_xW[2][MROWS][G3];   // per-dir input projections (reused L0/L1)
__device__ float g_z0[MROWS][D2];      // layer-0 output [b*T+t][256]
__device__ float g_z1[MROWS][D2];      // layer-1 output

// ---------------- input projection GEMM: C = A @ W^T + bias ----------------
// A: [MROWS, K] row-major (K = 64 for layer0 [x], 256 for layer1 [g_z0])
// W: [384, K] row-major, bias: [384] ;  writes g_xW[dir][m][n];  grid.z = dir
__global__ __launch_bounds__(256)
void proj_gemm_kernel(const float* __restrict__ A0,
                      const float* __restrict__ Wf, const float* __restrict__ Wb,
                      const float* __restrict__ bf, const float* __restrict__ bb,
                      int K, int layer)
{
    constexpr int BM = 128, BN = 64, BK = 16;
    __shared__ __align__(16) float As[BK][BM + 4];
    __shared__ __align__(16) float Ws[BK][BN + 4];

    const int dir = blockIdx.z;
    const float* __restrict__ A    = layer ? (const float*)g_z0 : A0;
    const float* __restrict__ Wp   = dir ? Wb : Wf;
    const float* __restrict__ bias = dir ? bb : bf;

    const int m0 = blockIdx.x * BM;
    const int n0 = blockIdx.y * BN;

    const int tid  = threadIdx.x;
    const int arow = tid >> 2;           // 0..63
    const int kq   = (tid & 3) * 4;      // 0,4,8,12
    const int tx   = tid & 15;           // N micro (4)
    const int ty   = tid >> 4;           // M micro (8 rows = 4 f32x2 pairs)

    ull acc2[4][4];                      // [m_pair][n]
    #pragma unroll
    for (int i = 0; i < 4; ++i)
        #pragma unroll
        for (int j = 0; j < 4; ++j) acc2[i][j] = 0ull;

    for (int k0 = 0; k0 < K; k0 += BK) {
        // load A tile (128 x 16) transposed into As
        {
            const float* p = A + (size_t)(m0 + arow) * K + k0 + kq;
            float4 v0 = *(const float4*)p;
            float4 v1 = *(const float4*)(p + (size_t)64 * K);
            As[kq + 0][arow] = v0.x; As[kq + 1][arow] = v0.y;
            As[kq + 2][arow] = v0.z; As[kq + 3][arow] = v0.w;
            As[kq + 0][arow + 64] = v1.x; As[kq + 1][arow + 64] = v1.y;
            As[kq + 2][arow + 64] = v1.z; As[kq + 3][arow + 64] = v1.w;
        }
        // load W tile (64 x 16) transposed into Ws
        {
            const float* p = Wp + (size_t)(n0 + arow) * K + k0 + kq;
            float4 v = *(const float4*)p;
            Ws[kq + 0][arow] = v.x; Ws[kq + 1][arow] = v.y;
            Ws[kq + 2][arow] = v.z; Ws[kq + 3][arow] = v.w;
        }
        __syncthreads();

        #pragma unroll
        for (int kk = 0; kk < BK; ++kk) {
            ulonglong2 a01 = *(const ulonglong2*)&As[kk][ty * 8];      // m pairs (0,1),(2,3)
            ulonglong2 a23 = *(const ulonglong2*)&As[kk][ty * 8 + 4];  // m pairs (4,5),(6,7)
            float4 w4 = *(const float4*)&Ws[kk][tx * 4];
            ull am[4] = {a01.x, a01.y, a23.x, a23.y};
            ull wp[4] = {pack2(w4.x, w4.x), pack2(w4.y, w4.y),
                         pack2(w4.z, w4.z), pack2(w4.w, w4.w)};
            #pragma unroll
            for (int i = 0; i < 4; ++i)
                #pragma unroll
                for (int j = 0; j < 4; ++j)
                    acc2[i][j] = fma2(am[i], wp[j], acc2[i][j]);
        }
        __syncthreads();
    }

    float* Cout = &g_xW[dir][0][0];
    float4 b4 = *(const float4*)(bias + n0 + tx * 4);
    float* Crow = Cout + (size_t)(m0 + ty * 8) * G3 + n0 + tx * 4;
    #pragma unroll
    for (int i = 0; i < 4; ++i) {
        float2 c0 = unpack2(acc2[i][0]);
        float2 c1 = unpack2(acc2[i][1]);
        float2 c2 = unpack2(acc2[i][2]);
        float2 c3 = unpack2(acc2[i][3]);
        float4 lo = {c0.x + b4.x, c1.x + b4.y, c2.x + b4.z, c3.x + b4.w};
        float4 hi = {c0.y + b4.x, c1.y + b4.y, c2.y + b4.z, c3.y + b4.w};
        *(float4*)(Crow + (size_t)(2 * i)     * G3) = lo;
        *(float4*)(Crow + (size_t)(2 * i + 1) * G3) = hi;
    }
}

// ---------------- GRU recurrence -------------------------------------------
// one block per (batch, dir); 384 threads, Whh row-per-thread as 64 f32x2 regs
__global__ __launch_bounds__(384, 1)
void gru_scan_kernel(const float* __restrict__ whh_f, const float* __restrict__ whh_b,
                     const float* __restrict__ bhh_f, const float* __restrict__ bhh_b,
                     int layer)
{
    const int b   = blockIdx.x >> 1;
    const int dir = blockIdx.x & 1;
    const int j   = threadIdx.x;                 // 0..383

    const float* __restrict__ whh = dir ? whh_b : whh_f;
    const float* __restrict__ bhh = dir ? bhh_b : bhh_f;

    __shared__ __align__(16) float h_s[HID];
    __shared__ float gh_s[G3];

    // load Whh row j into 64 packed f32x2 registers
    ull w2[64];
    #pragma unroll
    for (int i = 0; i < 64; i += 2) {
        ulonglong2 v = *(const ulonglong2*)(whh + (size_t)j * HID + 2 * i);
        w2[i] = v.x; w2[i + 1] = v.y;
    }
    const float bj = bhh[j];
    float hreg = 0.f;
    if (j < HID) h_s[j] = 0.f;

    const float* __restrict__ gi = &g_xW[dir][(size_t)b * TT][0];
    float* __restrict__ zout = (layer ? &g_z1[(size_t)b * TT][0]
                                      : &g_z0[(size_t)b * TT][0]);
    __syncthreads();

    for (int t = 0; t < TT; ++t) {
        const int tt = dir ? (TT - 1 - t) : t;

        // gate threads prefetch their 3 input-projection values (latency
        // hidden under the dot phase); other warps skip entirely
        float gi_r, gi_z, gi_n;
        if (j < HID) {
            const float* gp = gi + (size_t)tt * G3 + j;
            gi_r = __ldg(gp);
            gi_z = __ldg(gp + HID);
            gi_n = __ldg(gp + 2 * HID);
        }

        // gh[j] = Whh[j,:] . h  via packed FFMA2 (4 independent chains)
        ull a0 = pack2(bj, 0.f), a1 = 0ull, a2 = 0ull, a3 = 0ull;
        const ull* h2 = (const ull*)h_s;
        #pragma unroll
        for (int i = 0; i < 64; i += 4) {
            ulonglong2 hv0 = *(const ulonglong2*)(h2 + i);
            ulonglong2 hv1 = *(const ulonglong2*)(h2 + i + 2);
            a0 = fma2(w2[i],     hv0.x, a0);
            a1 = fma2(w2[i + 1], hv0.y, a1);
            a2 = fma2(w2[i + 2], hv1.x, a2);
            a3 = fma2(w2[i + 3], hv1.y, a3);
        }
        float2 s0 = unpack2(a0), s1 = unpack2(a1), s2 = unpack2(a2), s3 = unpack2(a3);
        gh_s[j] = ((s0.x + s0.y) + (s1.x + s1.y)) + ((s2.x + s2.y) + (s3.x + s3.y));
        __syncthreads();

        if (j < HID) {
            float r  = sigm(gi_r + gh_s[j]);
            float zg = sigm(gi_z + gh_s[HID + j]);
            float n  = ftanh(gi_n + r * gh_s[2 * HID + j]);
            hreg = (1.f - zg) * n + zg * hreg;
            h_s[j] = hreg;
            zout[(size_t)tt * D2 + dir * HID + j] = hreg;
        }
        __syncthreads();
    }
}

// ---------------- attention pooling + heads --------------------------------
__global__ __launch_bounds__(256)
void attn_head_kernel(const float* __restrict__ attn_w, const float* __restrict__ attn_b,
                      const float* __restrict__ motor_w, const float* __restrict__ motor_b,
                      const float* __restrict__ state_w, const float* __restrict__ state_b,
                      const int* __restrict__ motor_k, float* __restrict__ out)
{
    const int b = blockIdx.x;
    const int tid = threadIdx.x;       // 256 threads
    const int warp = tid >> 5, lane = tid & 31;

    __shared__ float sw[D2];
    __shared__ float sc[TT];
    __shared__ float red[256];
    __shared__ float pooled[D2];

    sw[tid] = attn_w[tid];
    __syncthreads();

    const float* __restrict__ zb = &g_z1[(size_t)b * TT][0];
    const float ab = attn_b[0];

    // scores[t] = z[b,t,:] . attn_w + attn_b
    for (int t = warp; t < TT; t += 8) {
        const float* zt = zb + (size_t)t * D2;
        float s = 0.f;
        #pragma unroll
        for (int d = lane; d < D2; d += 32) s += zt[d] * sw[d];
        #pragma unroll
        for (int o = 16; o; o >>= 1) s += __shfl_xor_sync(0xffffffffu, s, o);
        if (lane == 0) sc[t] = s + ab;
    }
    __syncthreads();

    // softmax over T
    float m = -INFINITY;
    for (int t = tid; t < TT; t += 256) m = fmaxf(m, sc[t]);
    red[tid] = m; __syncthreads();
    for (int s = 128; s; s >>= 1) {
        if (tid < s) red[tid] = fmaxf(red[tid], red[tid + s]);
        __syncthreads();
    }
    m = red[0]; __syncthreads();

    float sum = 0.f;
    for (int t = tid; t < TT; t += 256) {
        float e = __expf(sc[t] - m);
        sc[t] = e;
        sum += e;
    }
    red[tid] = sum; __syncthreads();
    for (int s = 128; s; s >>= 1) {
        if (tid < s) red[tid] += red[tid + s];
        __syncthreads();
    }
    const float inv = 1.f / red[0];
    __syncthreads();

    // pooled[d] = sum_t a[t] * z[b,t,d]
    float acc = 0.f;
    #pragma unroll 8
    for (int t = 0; t < TT; ++t) acc += sc[t] * zb[(size_t)t * D2 + tid];
    pooled[tid] = acc * inv;
    __syncthreads();

    // heads: 5 motor logits + 2 state logits, one warp each
    if (warp < 7) {
        const float* wv;
        float bv;
        int mk = motor_k[b];
        if (warp < 5) { wv = motor_w + warp * D2;              bv = motor_b[warp]; }
        else          { int c = warp - 5;
                        wv = state_w + (size_t)(mk * 2 + c) * D2;
                        bv = state_b[mk * 2 + c]; }
        float s = 0.f;
        #pragma unroll
        for (int d = lane; d < D2; d += 32) s += pooled[d] * wv[d];
        #pragma unroll
        for (int o = 16; o; o >>= 1) s += __shfl_xor_sync(0xffffffffu, s, o);
        if (lane == 0) {
            if (warp < 5) out[b * 5 + warp] = s + bv;
            else          out[BATCH * 5 + b * 2 + (warp - 5)] = s + bv;
        }
    }
}

// ---------------- launch ----------------------------------------------------
extern "C" void kernel_launch(void* const* d_in, const int* in_sizes, int n_in,
                              void* d_out, int out_size)
{
    const float* x        = (const float*)d_in[0];
    const int*   motor_k  = (const int*)  d_in[1];
    const float* wih_l0f  = (const float*)d_in[2];
    const float* whh_l0f  = (const float*)d_in[3];
    const float* bih_l0f  = (const float*)d_in[4];
    const float* bhh_l0f  = (const float*)d_in[5];
    const float* wih_l0b  = (const float*)d_in[6];
    const float* whh_l0b  = (const float*)d_in[7];
    const float* bih_l0b  = (const float*)d_in[8];
    const float* bhh_l0b  = (const float*)d_in[9];
    const float* wih_l1f  = (const float*)d_in[10];
    const float* whh_l1f  = (const float*)d_in[11];
    const float* bih_l1f  = (const float*)d_in[12];
    const float* bhh_l1f  = (const float*)d_in[13];
    const float* wih_l1b  = (const float*)d_in[14];
    const float* whh_l1b  = (const float*)d_in[15];
    const float* bih_l1b  = (const float*)d_in[16];
    const float* bhh_l1b  = (const float*)d_in[17];
    const float* attn_w   = (const float*)d_in[18];
    const float* attn_b   = (const float*)d_in[19];
    const float* motor_w  = (const float*)d_in[20];
    const float* motor_b  = (const float*)d_in[21];
    const float* state_w  = (const float*)d_in[22];
    const float* state_b  = (const float*)d_in[23];
    float* out = (float*)d_out;

    dim3 gproj(MROWS / 128, G3 / 64, 2);

    // layer 0
    proj_gemm_kernel<<<gproj, 256>>>(x, wih_l0f, wih_l0b, bih_l0f, bih_l0b, DIN, 0);
    gru_scan_kernel<<<BATCH * 2, 384>>>(whh_l0f, whh_l0b, bhh_l0f, bhh_l0b, 0);
    // layer 1
    proj_gemm_kernel<<<gproj, 256>>>(nullptr, wih_l1f, wih_l1b, bih_l1f, bih_l1b, D2, 1);
    gru_scan_kernel<<<BATCH * 2, 384>>>(whh_l1f, whh_l1b, bhh_l1f, bhh_l1b, 1);
    // pooling + heads
    attn_head_kernel<<<BATCH, 256>>>(attn_w, attn_b, motor_w, motor_b,
                                     state_w, state_b, motor_k, out);
}